// round 1
// baseline (speedup 1.0000x reference)
#include <cuda_runtime.h>

#define HIDDEN 768
#define META 25
#define NMENT 2000
#define NPAIRS 40000
#define BATCH 2
#define MROWS (BATCH * NMENT)     // 4000
#define NCOLS (2 * HIDDEN)        // 1536
#define EDC 300

// Scratch (static device globals; no allocation allowed)
__device__ float g_P[MROWS * NCOLS];   // 24.6 MB: [4000, 1536] = M @ [W1a | W1b]
__device__ float g_W[HIDDEN * NCOLS];  // 4.7 MB : packed [768, 1536] weight
__device__ float g_E[EDC * HIDDEN];    // 0.92 MB: ed_table @ W1c + b1

// ---------------------------------------------------------------------------
// Pack Wcat[k][j] : j<768 -> W1[k][j] ; else -> W1[768+k][j-768]
// W1 is [1561, 768] row-major.
// ---------------------------------------------------------------------------
__global__ void pack_w_kernel(const float* __restrict__ W1) {
    int idx = blockIdx.x * blockDim.x + threadIdx.x;
    if (idx >= HIDDEN * NCOLS) return;
    int k = idx / NCOLS;
    int j = idx % NCOLS;
    float v;
    if (j < HIDDEN) v = W1[(size_t)k * HIDDEN + j];
    else            v = W1[(size_t)(HIDDEN + k) * HIDDEN + (j - HIDDEN)];
    g_W[idx] = v;
}

// ---------------------------------------------------------------------------
// E[e][j] = sum_t ed_table[e][t] * W1[1536+t][j] + b1[j]
// ---------------------------------------------------------------------------
__global__ void ed_kernel(const float* __restrict__ ed_table,
                          const float* __restrict__ W1,
                          const float* __restrict__ b1) {
    int idx = blockIdx.x * blockDim.x + threadIdx.x;
    if (idx >= EDC * HIDDEN) return;
    int e = idx / HIDDEN;
    int j = idx % HIDDEN;
    float s = b1[j];
    #pragma unroll
    for (int t = 0; t < META; t++) {
        s += ed_table[e * META + t] * W1[(size_t)(2 * HIDDEN + t) * HIDDEN + j];
    }
    g_E[idx] = s;
}

// ---------------------------------------------------------------------------
// SGEMM: g_P[4000,1536] = M[4000,768] @ g_W[768,1536]
// BM=BN=128, BK=8, 256 threads, 8x8 per-thread tile.
// ---------------------------------------------------------------------------
__global__ __launch_bounds__(256) void sgemm_kernel(const float* __restrict__ A) {
    __shared__ float As[8][128];
    __shared__ float Bs[8][128];

    const int bm = blockIdx.y;
    const int bn = blockIdx.x;
    const int tid = threadIdx.x;
    const int tx = tid % 16;       // 0..15  (N direction)
    const int ty = tid / 16;       // 0..15  (M direction)

    float acc[8][8];
    #pragma unroll
    for (int i = 0; i < 8; i++)
        #pragma unroll
        for (int j = 0; j < 8; j++) acc[i][j] = 0.f;

    // A tile load: 128 rows x 8 k, one float4 per thread
    const int aRow = tid / 2;              // 0..127
    const int aK4  = (tid % 2) * 4;        // 0 or 4
    const int gRowA = bm * 128 + aRow;
    const bool aValid = (gRowA < MROWS);
    const float* Aptr = A + (size_t)(aValid ? gRowA : 0) * HIDDEN;

    // B tile load: 8 k-rows x 128 cols, one float4 per thread
    const int bRow = tid / 32;             // 0..7
    const int bCol = (tid % 32) * 4;       // 0..124
    const float* Bbase = g_W + (size_t)bRow * NCOLS + bn * 128 + bCol;

    for (int k0 = 0; k0 < HIDDEN; k0 += 8) {
        float4 av = aValid ? *(const float4*)(Aptr + k0 + aK4)
                           : make_float4(0.f, 0.f, 0.f, 0.f);
        float4 bv = *(const float4*)(Bbase + (size_t)k0 * NCOLS);

        As[aK4 + 0][aRow] = av.x;
        As[aK4 + 1][aRow] = av.y;
        As[aK4 + 2][aRow] = av.z;
        As[aK4 + 3][aRow] = av.w;
        *(float4*)(&Bs[bRow][bCol]) = bv;
        __syncthreads();

        #pragma unroll
        for (int k = 0; k < 8; k++) {
            float rm[8], rn[8];
            #pragma unroll
            for (int i = 0; i < 8; i++) rm[i] = As[k][ty * 8 + i];
            #pragma unroll
            for (int j = 0; j < 8; j++) rn[j] = Bs[k][tx * 8 + j];
            #pragma unroll
            for (int i = 0; i < 8; i++)
                #pragma unroll
                for (int j = 0; j < 8; j++)
                    acc[i][j] += rm[i] * rn[j];
        }
        __syncthreads();
    }

    #pragma unroll
    for (int i = 0; i < 8; i++) {
        int m = bm * 128 + ty * 8 + i;
        if (m < MROWS) {
            float* Crow = g_P + (size_t)m * NCOLS + bn * 128 + tx * 8;
            *(float4*)(Crow + 0) = make_float4(acc[i][0], acc[i][1], acc[i][2], acc[i][3]);
            *(float4*)(Crow + 4) = make_float4(acc[i][4], acc[i][5], acc[i][6], acc[i][7]);
        }
    }
}

// ---------------------------------------------------------------------------
// Epilogue: one warp per pair.
// out[p] = relu(P[b,i0][0:768] + P[b,i1][768:1536] + E[e]) . W2 + b2
// ---------------------------------------------------------------------------
__global__ __launch_bounds__(256) void epilogue_kernel(
    const int* __restrict__ pairs,   // [B, P, 2]
    const int* __restrict__ eds,     // [B, P]
    const float* __restrict__ W2,    // [768]
    const float* __restrict__ b2,    // [1]
    float* __restrict__ out)         // [B*P]
{
    __shared__ float w2s[HIDDEN];
    const int tid = threadIdx.x;
    for (int i = tid; i < HIDDEN; i += 256) w2s[i] = W2[i];
    __syncthreads();

    const int warp = tid / 32;
    const int lane = tid % 32;
    const int p = blockIdx.x * 8 + warp;
    if (p >= BATCH * NPAIRS) return;

    const int b  = p / NPAIRS;
    const int i0 = pairs[(size_t)p * 2 + 0];
    const int i1 = pairs[(size_t)p * 2 + 1];
    const int e  = eds[p];

    const float* rowA = g_P + (size_t)(b * NMENT + i0) * NCOLS;
    const float* rowB = g_P + (size_t)(b * NMENT + i1) * NCOLS + HIDDEN;
    const float* rowE = g_E + (size_t)e * HIDDEN;

    float acc = 0.f;
    #pragma unroll
    for (int j0 = 0; j0 < HIDDEN; j0 += 128) {
        const int j = j0 + lane * 4;
        float4 a = *(const float4*)(rowA + j);
        float4 c = *(const float4*)(rowB + j);
        float4 d = *(const float4*)(rowE + j);
        float4 w = *(const float4*)(&w2s[j]);
        float v;
        v = a.x + c.x + d.x; acc += fmaxf(v, 0.f) * w.x;
        v = a.y + c.y + d.y; acc += fmaxf(v, 0.f) * w.y;
        v = a.z + c.z + d.z; acc += fmaxf(v, 0.f) * w.z;
        v = a.w + c.w + d.w; acc += fmaxf(v, 0.f) * w.w;
    }

    #pragma unroll
    for (int off = 16; off; off >>= 1)
        acc += __shfl_xor_sync(0xffffffff, acc, off);

    if (lane == 0) out[p] = acc + b2[0];
}

// ---------------------------------------------------------------------------
extern "C" void kernel_launch(void* const* d_in, const int* in_sizes, int n_in,
                              void* d_out, int out_size) {
    const float* mention_reprs = (const float*)d_in[0];  // [2,2000,768]
    const int*   pairs         = (const int*)d_in[1];    // [2,40000,2]
    const int*   eds           = (const int*)d_in[2];    // [2,40000]
    const float* ed_table      = (const float*)d_in[3];  // [300,25]
    const float* W1            = (const float*)d_in[4];  // [1561,768]
    const float* b1            = (const float*)d_in[5];  // [768]
    const float* W2            = (const float*)d_in[6];  // [768,1]
    const float* b2            = (const float*)d_in[7];  // [1]
    float* out = (float*)d_out;                          // [80000]

    // 1) pack weights
    {
        int total = HIDDEN * NCOLS;
        pack_w_kernel<<<(total + 255) / 256, 256>>>(W1);
    }
    // 2) ed projection + b1 fold
    {
        int total = EDC * HIDDEN;
        ed_kernel<<<(total + 255) / 256, 256>>>(ed_table, W1, b1);
    }
    // 3) SGEMM P = M @ Wcat
    {
        dim3 grid(NCOLS / 128, (MROWS + 127) / 128);  // (12, 32)
        sgemm_kernel<<<grid, 256>>>(mention_reprs);
    }
    // 4) per-pair epilogue
    {
        int npairs = BATCH * NPAIRS;
        epilogue_kernel<<<(npairs + 7) / 8, 256>>>(pairs, eds, W2, b2, out);
    }
}

// round 3
// speedup vs baseline: 1.7372x; 1.7372x over previous
#include <cuda_runtime.h>
#include <cuda_bf16.h>
#include <cstdint>

#define HIDDEN 768
#define META 25
#define NMENT 2000
#define NPAIRS 40000
#define BATCH 2
#define MROWS (BATCH * NMENT)     // 4000
#define MPAD 4096
#define NCOLS (2 * HIDDEN)        // 1536
#define EDC 300

// -------------------- scratch (static device globals) ----------------------
__device__ float g_P[MROWS * NCOLS];                     // 24.6 MB
__device__ float g_E[EDC * HIDDEN];                      // 0.92 MB
__device__ __nv_bfloat16 g_Ah[MPAD * HIDDEN];
__device__ __nv_bfloat16 g_Al[MPAD * HIDDEN];
__device__ __nv_bfloat16 g_Wth[NCOLS * HIDDEN];          // W^T packed, hi
__device__ __nv_bfloat16 g_Wtl[NCOLS * HIDDEN];          // W^T packed, lo

// ---------------------------------------------------------------------------
__global__ void convert_a_kernel(const float* __restrict__ M) {
    int idx = blockIdx.x * blockDim.x + threadIdx.x;
    if (idx >= MPAD * HIDDEN) return;
    int row = idx / HIDDEN;
    float v = (row < MROWS) ? M[idx] : 0.f;
    __nv_bfloat16 hi = __float2bfloat16(v);
    float lo = v - __bfloat162float(hi);
    g_Ah[idx] = hi;
    g_Al[idx] = __float2bfloat16(lo);
}

__global__ void convert_w_kernel(const float* __restrict__ W1) {
    __shared__ float t[32][33];
    const int kt = blockIdx.x * 32;
    const int nt = blockIdx.y * 32;
    const int srcRowBase = (nt < HIDDEN) ? 0 : HIDDEN;
    const int srcCol     = ((nt < HIDDEN) ? nt : nt - HIDDEN) + threadIdx.x;
    #pragma unroll
    for (int r = threadIdx.y; r < 32; r += 8) {
        int k = kt + r;
        t[r][threadIdx.x] = W1[(size_t)(srcRowBase + k) * HIDDEN + srcCol];
    }
    __syncthreads();
    #pragma unroll
    for (int r = threadIdx.y; r < 32; r += 8) {
        int n = nt + r;
        float v = t[threadIdx.x][r];
        __nv_bfloat16 hi = __float2bfloat16(v);
        float lo = v - __bfloat162float(hi);
        size_t o = (size_t)n * HIDDEN + kt + threadIdx.x;
        g_Wth[o] = hi;
        g_Wtl[o] = __float2bfloat16(lo);
    }
}

__global__ void ed_kernel(const float* __restrict__ ed_table,
                          const float* __restrict__ W1,
                          const float* __restrict__ b1) {
    int idx = blockIdx.x * blockDim.x + threadIdx.x;
    if (idx >= EDC * HIDDEN) return;
    int e = idx / HIDDEN;
    int j = idx % HIDDEN;
    float s = b1[j];
    #pragma unroll
    for (int t = 0; t < META; t++)
        s += ed_table[e * META + t] * W1[(size_t)(2 * HIDDEN + t) * HIDDEN + j];
    g_E[idx] = s;
}

// ---------------------------------------------------------------------------
// mma.sync bf16 GEMM (legacy HMMA path; tcgen05 not available on this
// ptxas target). P[4000,1536] = Ah@Wth^T + Ah@Wtl^T + Al@Wth^T, fp32 accum.
// 128x128 CTA tile, BK=32, 3-stage cp.async, 80B-padded smem rows
// (conflict-free ldmatrix: 20r mod 32 covers all banks).
// ---------------------------------------------------------------------------
#define BK 32
#define KBLK (HIDDEN / BK)          // 24
#define NBLK (3 * KBLK)             // 72
#define ROWB 80
#define TILEB (128 * ROWB)          // 10240
#define STAGEB (2 * TILEB)          // 20480
#define STAGES 3
#define GEMM_SMEM (STAGES * STAGEB) // 61440

static __device__ __forceinline__ uint32_t smem_u32(const void* p) {
    uint32_t a;
    asm("{ .reg .u64 t; cvta.to.shared.u64 t, %1; cvt.u32.u64 %0, t; }" : "=r"(a) : "l"(p));
    return a;
}
static __device__ __forceinline__ void cp16(uint32_t dst, const void* src) {
    asm volatile("cp.async.cg.shared.global [%0], [%1], 16;" :: "r"(dst), "l"(src));
}
static __device__ __forceinline__ void ldmx4(uint32_t& r0, uint32_t& r1,
                                             uint32_t& r2, uint32_t& r3, uint32_t a) {
    asm volatile("ldmatrix.sync.aligned.m8n8.x4.shared.b16 {%0,%1,%2,%3}, [%4];"
                 : "=r"(r0), "=r"(r1), "=r"(r2), "=r"(r3) : "r"(a));
}
static __device__ __forceinline__ void mma16816(float* c, const uint32_t* a, const uint32_t* b) {
    asm volatile(
        "mma.sync.aligned.m16n8k16.row.col.f32.bf16.bf16.f32 "
        "{%0,%1,%2,%3}, {%4,%5,%6,%7}, {%8,%9}, {%0,%1,%2,%3};"
        : "+f"(c[0]), "+f"(c[1]), "+f"(c[2]), "+f"(c[3])
        : "r"(a[0]), "r"(a[1]), "r"(a[2]), "r"(a[3]), "r"(b[0]), "r"(b[1]));
}

__global__ __launch_bounds__(256) void mma_gemm_kernel() {
    extern __shared__ char smem[];
    const uint32_t sb = smem_u32(smem);
    const int tid = threadIdx.x;
    const int lane = tid & 31;
    const int wid = tid >> 5;
    const int m0 = blockIdx.y * 128;
    const int n0 = blockIdx.x * 128;
    const int warpM = wid & 1;       // 2 warps in M
    const int warpN = wid >> 1;      // 4 warps in N

    const int ldRow = tid >> 1;      // 0..127
    const int ldSeg = (tid & 1) * 2; // 0 or 2 (16B segs)

    float acc[4][4][4];
    #pragma unroll
    for (int i = 0; i < 4; i++)
        #pragma unroll
        for (int j = 0; j < 4; j++)
            #pragma unroll
            for (int q = 0; q < 4; q++) acc[i][j][q] = 0.f;

    auto issue_load = [&](int blk) {
        const int stage = blk % STAGES;
        const int pass = blk / KBLK;
        const int kk = blk % KBLK;
        const __nv_bfloat16* Asrc = (pass == 2) ? g_Al : g_Ah;
        const __nv_bfloat16* Bsrc = (pass == 1) ? g_Wtl : g_Wth;
        const __nv_bfloat16* ga = Asrc + (size_t)(m0 + ldRow) * HIDDEN + kk * BK + ldSeg * 8;
        const __nv_bfloat16* gb = Bsrc + (size_t)(n0 + ldRow) * HIDDEN + kk * BK + ldSeg * 8;
        uint32_t da = sb + stage * STAGEB + ldRow * ROWB + ldSeg * 16;
        uint32_t db = da + TILEB;
        cp16(da, ga);       cp16(da + 16, ga + 8);
        cp16(db, gb);       cp16(db + 16, gb + 8);
        asm volatile("cp.async.commit_group;" ::: "memory");
    };

    issue_load(0);
    issue_load(1);

    for (int blk = 0; blk < NBLK; blk++) {
        const int stage = blk % STAGES;
        asm volatile("cp.async.wait_group 1;" ::: "memory");
        __syncthreads();
        if (blk + 2 < NBLK) issue_load(blk + 2);

        const uint32_t Abase = sb + stage * STAGEB;
        const uint32_t Bbase = Abase + TILEB;

        #pragma unroll
        for (int ks = 0; ks < 2; ks++) {
            const int kb = ks * 32;  // byte offset of k16 step
            uint32_t a[4][4], b[4][2];
            #pragma unroll
            for (int mf = 0; mf < 4; mf++) {
                uint32_t addr = Abase + (warpM * 64 + mf * 16 + (lane & 15)) * ROWB
                              + kb + (lane >> 4) * 16;
                ldmx4(a[mf][0], a[mf][1], a[mf][2], a[mf][3], addr);
            }
            #pragma unroll
            for (int nf2 = 0; nf2 < 2; nf2++) {
                const int g = lane >> 3;
                const int r = lane & 7;
                uint32_t addr = Bbase
                    + (warpN * 32 + nf2 * 16 + ((g >> 1) * 8 + r)) * ROWB
                    + kb + (g & 1) * 16;
                ldmx4(b[nf2 * 2][0], b[nf2 * 2][1],
                      b[nf2 * 2 + 1][0], b[nf2 * 2 + 1][1], addr);
            }
            #pragma unroll
            for (int mf = 0; mf < 4; mf++)
                #pragma unroll
                for (int nf = 0; nf < 4; nf++)
                    mma16816(acc[mf][nf], a[mf], b[nf]);
        }
    }

    // epilogue: write valid rows of P
    #pragma unroll
    for (int mf = 0; mf < 4; mf++) {
        const int r0 = m0 + warpM * 64 + mf * 16 + (lane >> 2);
        #pragma unroll
        for (int nf = 0; nf < 4; nf++) {
            const int c = n0 + warpN * 32 + nf * 8 + (lane & 3) * 2;
            if (r0 < MROWS)
                *(float2*)(g_P + (size_t)r0 * NCOLS + c) =
                    make_float2(acc[mf][nf][0], acc[mf][nf][1]);
            if (r0 + 8 < MROWS)
                *(float2*)(g_P + (size_t)(r0 + 8) * NCOLS + c) =
                    make_float2(acc[mf][nf][2], acc[mf][nf][3]);
        }
    }
}

// ---------------------------------------------------------------------------
// Epilogue: one warp per pair.
// ---------------------------------------------------------------------------
__global__ __launch_bounds__(256) void epilogue_kernel(
    const int* __restrict__ pairs, const int* __restrict__ eds,
    const float* __restrict__ W2, const float* __restrict__ b2,
    float* __restrict__ out)
{
    __shared__ float w2s[HIDDEN];
    const int tid = threadIdx.x;
    for (int i = tid; i < HIDDEN; i += 256) w2s[i] = W2[i];
    __syncthreads();

    const int warp = tid / 32;
    const int lane = tid % 32;
    const int p = blockIdx.x * 8 + warp;
    if (p >= BATCH * NPAIRS) return;

    const int b  = p / NPAIRS;
    const int i0 = pairs[(size_t)p * 2 + 0];
    const int i1 = pairs[(size_t)p * 2 + 1];
    const int e  = eds[p];

    const float* rowA = g_P + (size_t)(b * NMENT + i0) * NCOLS;
    const float* rowB = g_P + (size_t)(b * NMENT + i1) * NCOLS + HIDDEN;
    const float* rowE = g_E + (size_t)e * HIDDEN;

    float acc = 0.f;
    #pragma unroll
    for (int j0 = 0; j0 < HIDDEN; j0 += 128) {
        const int j = j0 + lane * 4;
        float4 a = *(const float4*)(rowA + j);
        float4 c = *(const float4*)(rowB + j);
        float4 d = *(const float4*)(rowE + j);
        float4 w = *(const float4*)(&w2s[j]);
        float v;
        v = a.x + c.x + d.x; acc += fmaxf(v, 0.f) * w.x;
        v = a.y + c.y + d.y; acc += fmaxf(v, 0.f) * w.y;
        v = a.z + c.z + d.z; acc += fmaxf(v, 0.f) * w.z;
        v = a.w + c.w + d.w; acc += fmaxf(v, 0.f) * w.w;
    }
    #pragma unroll
    for (int off = 16; off; off >>= 1)
        acc += __shfl_xor_sync(0xffffffff, acc, off);
    if (lane == 0) out[p] = acc + b2[0];
}

// ---------------------------------------------------------------------------
extern "C" void kernel_launch(void* const* d_in, const int* in_sizes, int n_in,
                              void* d_out, int out_size) {
    const float* mention_reprs = (const float*)d_in[0];
    const int*   pairs         = (const int*)d_in[1];
    const int*   eds           = (const int*)d_in[2];
    const float* ed_table      = (const float*)d_in[3];
    const float* W1            = (const float*)d_in[4];
    const float* b1            = (const float*)d_in[5];
    const float* W2            = (const float*)d_in[6];
    const float* b2            = (const float*)d_in[7];
    float* out = (float*)d_out;

    cudaFuncSetAttribute(mma_gemm_kernel,
                         cudaFuncAttributeMaxDynamicSharedMemorySize, GEMM_SMEM);

    { int total = MPAD * HIDDEN;
      convert_a_kernel<<<(total + 255) / 256, 256>>>(mention_reprs); }
    { dim3 grid(HIDDEN / 32, NCOLS / 32);
      convert_w_kernel<<<grid, dim3(32, 8)>>>(W1); }
    { int total = EDC * HIDDEN;
      ed_kernel<<<(total + 255) / 256, 256>>>(ed_table, W1, b1); }
    { dim3 grid(NCOLS / 128, MPAD / 128);  // (12, 32)
      mma_gemm_kernel<<<grid, 256, GEMM_SMEM>>>(); }
    { int npairs = BATCH * NPAIRS;
      epilogue_kernel<<<(npairs + 7) / 8, 256>>>(pairs, eds, W2, b2, out); }
}

// round 5
// speedup vs baseline: 2.2248x; 1.2807x over previous
#include <cuda_runtime.h>
#include <cuda_fp16.h>
#include <cstdint>

#define HIDDEN 768
#define META 25
#define NMENT 2000
#define NPAIRS 40000
#define BATCH 2
#define MROWS (BATCH * NMENT)     // 4000
#define MPAD 4096
#define NCOLS (2 * HIDDEN)        // 1536
#define EDC 300

// -------------------- scratch (static device globals) ----------------------
__device__ __half g_Ph[MROWS * NCOLS];        // 12.3 MB  P in fp16
__device__ float  g_E[EDC * HIDDEN];          // 0.92 MB
__device__ __half g_Ah[MPAD * HIDDEN];        // fp16 hi of mentions
__device__ __half g_Al[MPAD * HIDDEN];        // fp16 lo of mentions
__device__ __half g_Wt[NCOLS * HIDDEN];       // W^T packed, fp16

// ---------------------------------------------------------------------------
__global__ void convert_a_kernel(const float* __restrict__ M) {
    int idx = blockIdx.x * blockDim.x + threadIdx.x;
    if (idx >= MPAD * HIDDEN) return;
    int row = idx / HIDDEN;
    float v = (row < MROWS) ? M[idx] : 0.f;
    __half hi = __float2half(v);
    float lo = v - __half2float(hi);
    g_Ah[idx] = hi;
    g_Al[idx] = __float2half(lo);
}

__global__ void convert_w_kernel(const float* __restrict__ W1) {
    __shared__ float t[32][33];
    const int kt = blockIdx.x * 32;
    const int nt = blockIdx.y * 32;
    const int srcRowBase = (nt < HIDDEN) ? 0 : HIDDEN;
    const int srcCol     = ((nt < HIDDEN) ? nt : nt - HIDDEN) + threadIdx.x;
    #pragma unroll
    for (int r = threadIdx.y; r < 32; r += 8) {
        int k = kt + r;
        t[r][threadIdx.x] = W1[(size_t)(srcRowBase + k) * HIDDEN + srcCol];
    }
    __syncthreads();
    #pragma unroll
    for (int r = threadIdx.y; r < 32; r += 8) {
        int n = nt + r;
        g_Wt[(size_t)n * HIDDEN + kt + threadIdx.x] = __float2half(t[threadIdx.x][r]);
    }
}

__global__ void ed_kernel(const float* __restrict__ ed_table,
                          const float* __restrict__ W1,
                          const float* __restrict__ b1) {
    int idx = blockIdx.x * blockDim.x + threadIdx.x;
    if (idx >= EDC * HIDDEN) return;
    int e = idx / HIDDEN;
    int j = idx % HIDDEN;
    float s = b1[j];
    #pragma unroll
    for (int t = 0; t < META; t++)
        s += ed_table[e * META + t] * W1[(size_t)(2 * HIDDEN + t) * HIDDEN + j];
    g_E[idx] = s;
}

// ---------------------------------------------------------------------------
// fp16 mma.sync GEMM: P = (Ah + Al) @ Wt^T, fp32 accum, fp16 store.
// 128x128 CTA tile, BK=32, 24 k-blocks, per-stage {Ah, Al, B} tiles,
// 3-stage cp.async pipeline, 80B-padded smem rows (conflict-free ldmatrix).
// ---------------------------------------------------------------------------
#define BK 32
#define NBLK (HIDDEN / BK)          // 24
#define ROWB 80
#define TILEB (128 * ROWB)          // 10240
#define STAGEB (3 * TILEB)          // 30720 (Ah, Al, B)
#define STAGES 3
#define GEMM_SMEM (STAGES * STAGEB) // 92160

static __device__ __forceinline__ uint32_t smem_u32(const void* p) {
    uint32_t a;
    asm("{ .reg .u64 t; cvta.to.shared.u64 t, %1; cvt.u32.u64 %0, t; }" : "=r"(a) : "l"(p));
    return a;
}
static __device__ __forceinline__ void cp16(uint32_t dst, const void* src) {
    asm volatile("cp.async.cg.shared.global [%0], [%1], 16;" :: "r"(dst), "l"(src));
}
static __device__ __forceinline__ void ldmx4(uint32_t& r0, uint32_t& r1,
                                             uint32_t& r2, uint32_t& r3, uint32_t a) {
    asm volatile("ldmatrix.sync.aligned.m8n8.x4.shared.b16 {%0,%1,%2,%3}, [%4];"
                 : "=r"(r0), "=r"(r1), "=r"(r2), "=r"(r3) : "r"(a));
}
static __device__ __forceinline__ void mma16816(float* c, const uint32_t* a, const uint32_t* b) {
    asm volatile(
        "mma.sync.aligned.m16n8k16.row.col.f32.f16.f16.f32 "
        "{%0,%1,%2,%3}, {%4,%5,%6,%7}, {%8,%9}, {%0,%1,%2,%3};"
        : "+f"(c[0]), "+f"(c[1]), "+f"(c[2]), "+f"(c[3])
        : "r"(a[0]), "r"(a[1]), "r"(a[2]), "r"(a[3]), "r"(b[0]), "r"(b[1]));
}

__global__ __launch_bounds__(256) void mma_gemm_kernel() {
    extern __shared__ char smem[];
    const uint32_t sb = smem_u32(smem);
    const int tid = threadIdx.x;
    const int lane = tid & 31;
    const int wid = tid >> 5;
    const int m0 = blockIdx.y * 128;
    const int n0 = blockIdx.x * 128;
    const int warpM = wid & 1;       // 2 warps in M
    const int warpN = wid >> 1;      // 4 warps in N

    const int ldRow = tid >> 1;      // 0..127
    const int ldSeg = (tid & 1) * 2; // 0 or 2 (16B segs)

    float acc[4][4][4];
    #pragma unroll
    for (int i = 0; i < 4; i++)
        #pragma unroll
        for (int j = 0; j < 4; j++)
            #pragma unroll
            for (int q = 0; q < 4; q++) acc[i][j][q] = 0.f;

    auto issue_load = [&](int blk) {
        const int stage = blk % STAGES;
        const __half* gah = g_Ah + (size_t)(m0 + ldRow) * HIDDEN + blk * BK + ldSeg * 8;
        const __half* gal = g_Al + (size_t)(m0 + ldRow) * HIDDEN + blk * BK + ldSeg * 8;
        const __half* gb  = g_Wt + (size_t)(n0 + ldRow) * HIDDEN + blk * BK + ldSeg * 8;
        uint32_t d = sb + stage * STAGEB + ldRow * ROWB + ldSeg * 16;
        cp16(d,              gah);  cp16(d + 16,              gah + 8);
        cp16(d + TILEB,      gal);  cp16(d + TILEB + 16,      gal + 8);
        cp16(d + 2 * TILEB,  gb);   cp16(d + 2 * TILEB + 16,  gb + 8);
        asm volatile("cp.async.commit_group;" ::: "memory");
    };

    issue_load(0);
    issue_load(1);

    for (int blk = 0; blk < NBLK; blk++) {
        const int stage = blk % STAGES;
        asm volatile("cp.async.wait_group 1;" ::: "memory");
        __syncthreads();
        if (blk + 2 < NBLK) issue_load(blk + 2);

        const uint32_t AhB = sb + stage * STAGEB;
        const uint32_t AlB = AhB + TILEB;
        const uint32_t Bb  = AhB + 2 * TILEB;

        #pragma unroll
        for (int ks = 0; ks < 2; ks++) {
            const int kb = ks * 32;  // byte offset of k16 step
            uint32_t ah[4][4], al[4][4], b[4][2];
            #pragma unroll
            for (int nf2 = 0; nf2 < 2; nf2++) {
                const int g = lane >> 3;
                const int r = lane & 7;
                uint32_t addr = Bb
                    + (warpN * 32 + nf2 * 16 + ((g >> 1) * 8 + r)) * ROWB
                    + kb + (g & 1) * 16;
                ldmx4(b[nf2 * 2][0], b[nf2 * 2][1],
                      b[nf2 * 2 + 1][0], b[nf2 * 2 + 1][1], addr);
            }
            #pragma unroll
            for (int mf = 0; mf < 4; mf++) {
                uint32_t roff = (warpM * 64 + mf * 16 + (lane & 15)) * ROWB
                              + kb + (lane >> 4) * 16;
                ldmx4(ah[mf][0], ah[mf][1], ah[mf][2], ah[mf][3], AhB + roff);
                ldmx4(al[mf][0], al[mf][1], al[mf][2], al[mf][3], AlB + roff);
            }
            #pragma unroll
            for (int mf = 0; mf < 4; mf++)
                #pragma unroll
                for (int nf = 0; nf < 4; nf++) {
                    mma16816(acc[mf][nf], ah[mf], b[nf]);
                    mma16816(acc[mf][nf], al[mf], b[nf]);
                }
        }
    }

    // store P as fp16
    #pragma unroll
    for (int mf = 0; mf < 4; mf++) {
        const int r0 = m0 + warpM * 64 + mf * 16 + (lane >> 2);
        #pragma unroll
        for (int nf = 0; nf < 4; nf++) {
            const int c = n0 + warpN * 32 + nf * 8 + (lane & 3) * 2;
            if (r0 < MROWS)
                *(__half2*)(g_Ph + (size_t)r0 * NCOLS + c) =
                    __floats2half2_rn(acc[mf][nf][0], acc[mf][nf][1]);
            if (r0 + 8 < MROWS)
                *(__half2*)(g_Ph + (size_t)(r0 + 8) * NCOLS + c) =
                    __floats2half2_rn(acc[mf][nf][2], acc[mf][nf][3]);
        }
    }
}

// ---------------------------------------------------------------------------
// Epilogue: one warp per pair; P rows in fp16, E rows in fp32.
// ---------------------------------------------------------------------------
__global__ __launch_bounds__(256) void epilogue_kernel(
    const int* __restrict__ pairs, const int* __restrict__ eds,
    const float* __restrict__ W2, const float* __restrict__ b2,
    float* __restrict__ out)
{
    __shared__ float w2s[HIDDEN];
    const int tid = threadIdx.x;
    for (int i = tid; i < HIDDEN; i += 256) w2s[i] = W2[i];
    __syncthreads();

    const int warp = tid / 32;
    const int lane = tid % 32;
    const int p = blockIdx.x * 8 + warp;
    if (p >= BATCH * NPAIRS) return;

    const int b  = p / NPAIRS;
    const int i0 = pairs[(size_t)p * 2 + 0];
    const int i1 = pairs[(size_t)p * 2 + 1];
    const int e  = eds[p];

    const __half* rowA = g_Ph + (size_t)(b * NMENT + i0) * NCOLS;
    const __half* rowB = g_Ph + (size_t)(b * NMENT + i1) * NCOLS + HIDDEN;
    const float*  rowE = g_E + (size_t)e * HIDDEN;

    float acc = 0.f;
    #pragma unroll
    for (int j0 = 0; j0 < 3; j0++) {
        const int h0 = j0 * 256 + lane * 8;   // half index, 16B aligned
        uint4 ua = *(const uint4*)(rowA + h0);
        uint4 ub = *(const uint4*)(rowB + h0);
        const __half2* ha = (const __half2*)&ua;
        const __half2* hb = (const __half2*)&ub;
        #pragma unroll
        for (int q = 0; q < 4; q++) {
            float2 fa = __half22float2(ha[q]);
            float2 fb = __half22float2(hb[q]);
            float2 fe = *(const float2*)(rowE + h0 + q * 2);
            float2 fw = *(const float2*)(&w2s[h0 + q * 2]);
            float v;
            v = fa.x + fb.x + fe.x; acc += fmaxf(v, 0.f) * fw.x;
            v = fa.y + fb.y + fe.y; acc += fmaxf(v, 0.f) * fw.y;
        }
    }
    #pragma unroll
    for (int off = 16; off; off >>= 1)
        acc += __shfl_xor_sync(0xffffffff, acc, off);
    if (lane == 0) out[p] = acc + b2[0];
}

// ---------------------------------------------------------------------------
extern "C" void kernel_launch(void* const* d_in, const int* in_sizes, int n_in,
                              void* d_out, int out_size) {
    const float* mention_reprs = (const float*)d_in[0];
    const int*   pairs         = (const int*)d_in[1];
    const int*   eds           = (const int*)d_in[2];
    const float* ed_table      = (const float*)d_in[3];
    const float* W1            = (const float*)d_in[4];
    const float* b1            = (const float*)d_in[5];
    const float* W2            = (const float*)d_in[6];
    const float* b2            = (const float*)d_in[7];
    float* out = (float*)d_out;

    cudaFuncSetAttribute(mma_gemm_kernel,
                         cudaFuncAttributeMaxDynamicSharedMemorySize, GEMM_SMEM);

    { int total = MPAD * HIDDEN;
      convert_a_kernel<<<(total + 255) / 256, 256>>>(mention_reprs); }
    { dim3 grid(HIDDEN / 32, NCOLS / 32);
      convert_w_kernel<<<grid, dim3(32, 8)>>>(W1); }
    { int total = EDC * HIDDEN;
      ed_kernel<<<(total + 255) / 256, 256>>>(ed_table, W1, b1); }
    { dim3 grid(NCOLS / 128, MPAD / 128);  // (12, 32)
      mma_gemm_kernel<<<grid, 256, GEMM_SMEM>>>(); }
    { int npairs = BATCH * NPAIRS;
      epilogue_kernel<<<(npairs + 7) / 8, 256>>>(pairs, eds, W2, b2, out); }
}

// round 6
// speedup vs baseline: 3.4245x; 1.5392x over previous
#include <cuda_runtime.h>
#include <cuda_fp16.h>
#include <cstdint>

#define HIDDEN 768
#define META 25
#define NMENT 2000
#define NPAIRS 40000
#define BATCH 2
#define MROWS (BATCH * NMENT)     // 4000
#define MPAD 4096
#define NCOLS (2 * HIDDEN)        // 1536
#define EDC 300

// -------------------- scratch (static device globals) ----------------------
__device__ __half g_Ph[MROWS * NCOLS];        // 12.3 MB  P in fp16
__device__ __half g_Eh[EDC * HIDDEN];         // 0.46 MB  E in fp16
__device__ __half g_Ah[MPAD * HIDDEN];        // fp16 mentions (padded)
__device__ __half g_Wt[NCOLS * HIDDEN];       // W^T packed, fp16

// ---------------------------------------------------------------------------
__global__ void convert_a_kernel(const float* __restrict__ M) {
    int idx = blockIdx.x * blockDim.x + threadIdx.x;
    if (idx >= MPAD * HIDDEN) return;
    int row = idx / HIDDEN;
    float v = (row < MROWS) ? M[idx] : 0.f;
    g_Ah[idx] = __float2half(v);
}

__global__ void convert_w_kernel(const float* __restrict__ W1) {
    __shared__ float t[32][33];
    const int kt = blockIdx.x * 32;
    const int nt = blockIdx.y * 32;
    const int srcRowBase = (nt < HIDDEN) ? 0 : HIDDEN;
    const int srcCol     = ((nt < HIDDEN) ? nt : nt - HIDDEN) + threadIdx.x;
    #pragma unroll
    for (int r = threadIdx.y; r < 32; r += 8) {
        int k = kt + r;
        t[r][threadIdx.x] = W1[(size_t)(srcRowBase + k) * HIDDEN + srcCol];
    }
    __syncthreads();
    #pragma unroll
    for (int r = threadIdx.y; r < 32; r += 8) {
        int n = nt + r;
        g_Wt[(size_t)n * HIDDEN + kt + threadIdx.x] = __float2half(t[threadIdx.x][r]);
    }
}

__global__ void ed_kernel(const float* __restrict__ ed_table,
                          const float* __restrict__ W1,
                          const float* __restrict__ b1) {
    int idx = blockIdx.x * blockDim.x + threadIdx.x;
    if (idx >= EDC * HIDDEN) return;
    int e = idx / HIDDEN;
    int j = idx % HIDDEN;
    float s = b1[j];
    #pragma unroll
    for (int t = 0; t < META; t++)
        s += ed_table[e * META + t] * W1[(size_t)(2 * HIDDEN + t) * HIDDEN + j];
    g_Eh[idx] = __float2half(s);
}

// ---------------------------------------------------------------------------
// fp16 mma.sync GEMM: P = A @ Wt^T, fp32 accum, fp16 store. Single pass.
// 128x128 CTA tile, BK=32, 24 k-blocks, {A, B} per stage, 4-stage cp.async,
// 80B-padded smem rows (conflict-free ldmatrix).
// ---------------------------------------------------------------------------
#define BK 32
#define NBLK (HIDDEN / BK)          // 24
#define ROWB 80
#define TILEB (128 * ROWB)          // 10240
#define STAGEB (2 * TILEB)          // 20480 (A, B)
#define STAGES 4
#define GEMM_SMEM (STAGES * STAGEB) // 81920

static __device__ __forceinline__ uint32_t smem_u32(const void* p) {
    uint32_t a;
    asm("{ .reg .u64 t; cvta.to.shared.u64 t, %1; cvt.u32.u64 %0, t; }" : "=r"(a) : "l"(p));
    return a;
}
static __device__ __forceinline__ void cp16(uint32_t dst, const void* src) {
    asm volatile("cp.async.cg.shared.global [%0], [%1], 16;" :: "r"(dst), "l"(src));
}
static __device__ __forceinline__ void ldmx4(uint32_t& r0, uint32_t& r1,
                                             uint32_t& r2, uint32_t& r3, uint32_t a) {
    asm volatile("ldmatrix.sync.aligned.m8n8.x4.shared.b16 {%0,%1,%2,%3}, [%4];"
                 : "=r"(r0), "=r"(r1), "=r"(r2), "=r"(r3) : "r"(a));
}
static __device__ __forceinline__ void mma16816(float* c, const uint32_t* a, const uint32_t* b) {
    asm volatile(
        "mma.sync.aligned.m16n8k16.row.col.f32.f16.f16.f32 "
        "{%0,%1,%2,%3}, {%4,%5,%6,%7}, {%8,%9}, {%0,%1,%2,%3};"
        : "+f"(c[0]), "+f"(c[1]), "+f"(c[2]), "+f"(c[3])
        : "r"(a[0]), "r"(a[1]), "r"(a[2]), "r"(a[3]), "r"(b[0]), "r"(b[1]));
}

__global__ __launch_bounds__(256) void mma_gemm_kernel() {
    extern __shared__ char smem[];
    const uint32_t sb = smem_u32(smem);
    const int tid = threadIdx.x;
    const int lane = tid & 31;
    const int wid = tid >> 5;
    const int m0 = blockIdx.y * 128;
    const int n0 = blockIdx.x * 128;
    const int warpM = wid & 1;       // 2 warps in M
    const int warpN = wid >> 1;      // 4 warps in N

    const int ldRow = tid >> 1;      // 0..127
    const int ldSeg = (tid & 1) * 2; // 0 or 2 (16B segs)

    float acc[4][4][4];
    #pragma unroll
    for (int i = 0; i < 4; i++)
        #pragma unroll
        for (int j = 0; j < 4; j++)
            #pragma unroll
            for (int q = 0; q < 4; q++) acc[i][j][q] = 0.f;

    auto issue_load = [&](int blk) {
        const int stage = blk % STAGES;
        const __half* ga = g_Ah + (size_t)(m0 + ldRow) * HIDDEN + blk * BK + ldSeg * 8;
        const __half* gb = g_Wt + (size_t)(n0 + ldRow) * HIDDEN + blk * BK + ldSeg * 8;
        uint32_t d = sb + stage * STAGEB + ldRow * ROWB + ldSeg * 16;
        cp16(d,         ga);  cp16(d + 16,         ga + 8);
        cp16(d + TILEB, gb);  cp16(d + TILEB + 16, gb + 8);
        asm volatile("cp.async.commit_group;" ::: "memory");
    };

    issue_load(0);
    issue_load(1);
    issue_load(2);

    for (int blk = 0; blk < NBLK; blk++) {
        const int stage = blk % STAGES;
        asm volatile("cp.async.wait_group 2;" ::: "memory");
        __syncthreads();
        if (blk + 3 < NBLK) issue_load(blk + 3);

        const uint32_t Ab = sb + stage * STAGEB;
        const uint32_t Bb = Ab + TILEB;

        #pragma unroll
        for (int ks = 0; ks < 2; ks++) {
            const int kb = ks * 32;  // byte offset of k16 step
            uint32_t a[4][4], b[4][2];
            #pragma unroll
            for (int nf2 = 0; nf2 < 2; nf2++) {
                const int g = lane >> 3;
                const int r = lane & 7;
                uint32_t addr = Bb
                    + (warpN * 32 + nf2 * 16 + ((g >> 1) * 8 + r)) * ROWB
                    + kb + (g & 1) * 16;
                ldmx4(b[nf2 * 2][0], b[nf2 * 2][1],
                      b[nf2 * 2 + 1][0], b[nf2 * 2 + 1][1], addr);
            }
            #pragma unroll
            for (int mf = 0; mf < 4; mf++) {
                uint32_t roff = (warpM * 64 + mf * 16 + (lane & 15)) * ROWB
                              + kb + (lane >> 4) * 16;
                ldmx4(a[mf][0], a[mf][1], a[mf][2], a[mf][3], Ab + roff);
            }
            #pragma unroll
            for (int mf = 0; mf < 4; mf++)
                #pragma unroll
                for (int nf = 0; nf < 4; nf++)
                    mma16816(acc[mf][nf], a[mf], b[nf]);
        }
    }

    // store P as fp16
    #pragma unroll
    for (int mf = 0; mf < 4; mf++) {
        const int r0 = m0 + warpM * 64 + mf * 16 + (lane >> 2);
        #pragma unroll
        for (int nf = 0; nf < 4; nf++) {
            const int c = n0 + warpN * 32 + nf * 8 + (lane & 3) * 2;
            if (r0 < MROWS)
                *(__half2*)(g_Ph + (size_t)r0 * NCOLS + c) =
                    __floats2half2_rn(acc[mf][nf][0], acc[mf][nf][1]);
            if (r0 + 8 < MROWS)
                *(__half2*)(g_Ph + (size_t)(r0 + 8) * NCOLS + c) =
                    __floats2half2_rn(acc[mf][nf][2], acc[mf][nf][3]);
        }
    }
}

// ---------------------------------------------------------------------------
// Epilogue: one warp per pair; P and E rows in fp16.
// ---------------------------------------------------------------------------
__global__ __launch_bounds__(256) void epilogue_kernel(
    const int* __restrict__ pairs, const int* __restrict__ eds,
    const float* __restrict__ W2, const float* __restrict__ b2,
    float* __restrict__ out)
{
    __shared__ float w2s[HIDDEN];
    const int tid = threadIdx.x;
    for (int i = tid; i < HIDDEN; i += 256) w2s[i] = W2[i];
    __syncthreads();

    const int warp = tid / 32;
    const int lane = tid % 32;
    const int p = blockIdx.x * 8 + warp;
    if (p >= BATCH * NPAIRS) return;

    const int b  = p / NPAIRS;
    const int i0 = pairs[(size_t)p * 2 + 0];
    const int i1 = pairs[(size_t)p * 2 + 1];
    const int e  = eds[p];

    const __half* rowA = g_Ph + (size_t)(b * NMENT + i0) * NCOLS;
    const __half* rowB = g_Ph + (size_t)(b * NMENT + i1) * NCOLS + HIDDEN;
    const __half* rowE = g_Eh + (size_t)e * HIDDEN;

    float acc = 0.f;
    #pragma unroll
    for (int j0 = 0; j0 < 3; j0++) {
        const int h0 = j0 * 256 + lane * 8;   // half index, 16B aligned
        uint4 ua = *(const uint4*)(rowA + h0);
        uint4 ub = *(const uint4*)(rowB + h0);
        uint4 ue = *(const uint4*)(rowE + h0);
        const __half2* ha = (const __half2*)&ua;
        const __half2* hb = (const __half2*)&ub;
        const __half2* he = (const __half2*)&ue;
        #pragma unroll
        for (int q = 0; q < 4; q++) {
            float2 fa = __half22float2(ha[q]);
            float2 fb = __half22float2(hb[q]);
            float2 fe = __half22float2(he[q]);
            float2 fw = *(const float2*)(&w2s[h0 + q * 2]);
            float v;
            v = fa.x + fb.x + fe.x; acc += fmaxf(v, 0.f) * fw.x;
            v = fa.y + fb.y + fe.y; acc += fmaxf(v, 0.f) * fw.y;
        }
    }
    #pragma unroll
    for (int off = 16; off; off >>= 1)
        acc += __shfl_xor_sync(0xffffffff, acc, off);
    if (lane == 0) out[p] = acc + b2[0];
}

// ---------------------------------------------------------------------------
extern "C" void kernel_launch(void* const* d_in, const int* in_sizes, int n_in,
                              void* d_out, int out_size) {
    const float* mention_reprs = (const float*)d_in[0];
    const int*   pairs         = (const int*)d_in[1];
    const int*   eds           = (const int*)d_in[2];
    const float* ed_table      = (const float*)d_in[3];
    const float* W1            = (const float*)d_in[4];
    const float* b1            = (const float*)d_in[5];
    const float* W2            = (const float*)d_in[6];
    const float* b2            = (const float*)d_in[7];
    float* out = (float*)d_out;

    cudaFuncSetAttribute(mma_gemm_kernel,
                         cudaFuncAttributeMaxDynamicSharedMemorySize, GEMM_SMEM);

    { int total = MPAD * HIDDEN;
      convert_a_kernel<<<(total + 255) / 256, 256>>>(mention_reprs); }
    { dim3 grid(HIDDEN / 32, NCOLS / 32);
      convert_w_kernel<<<grid, dim3(32, 8)>>>(W1); }
    { int total = EDC * HIDDEN;
      ed_kernel<<<(total + 255) / 256, 256>>>(ed_table, W1, b1); }
    { dim3 grid(NCOLS / 128, MPAD / 128);  // (12, 32)
      mma_gemm_kernel<<<grid, 256, GEMM_SMEM>>>(); }
    { int npairs = BATCH * NPAIRS;
      epilogue_kernel<<<(npairs + 7) / 8, 256>>>(pairs, eds, W2, b2, out); }
}

// round 7
// speedup vs baseline: 3.7416x; 1.0926x over previous
#include <cuda_runtime.h>
#include <cuda_fp16.h>
#include <cstdint>

#define HIDDEN 768
#define META 25
#define NMENT 2000
#define NPAIRS 40000
#define BATCH 2
#define MROWS (BATCH * NMENT)     // 4000
#define MPAD 4096
#define NCOLS (2 * HIDDEN)        // 1536
#define EDC 300

// -------------------- scratch (static device globals) ----------------------
__device__ __half g_Ph[MROWS * NCOLS];        // 12.3 MB  P in fp16
__device__ __half g_Eh[EDC * HIDDEN];         // 0.46 MB  E in fp16
__device__ __half g_Ah[MPAD * HIDDEN];        // fp16 mentions (padded)
__device__ __half g_Wt[NCOLS * HIDDEN];       // W^T packed, fp16

// ---------------------------------------------------------------------------
// Fused prep: [0, NBA)               convert A -> fp16 (zero-pad rows)
//             [NBA, NBA+NBW)         transpose+convert W -> g_Wt
//             [NBA+NBW, ...)         E = ed_table @ W1c + b1 -> fp16
// ---------------------------------------------------------------------------
#define NBA (MPAD * HIDDEN / 256)              // 12288
#define NBW ((HIDDEN / 32) * (NCOLS / 32))     // 24*48 = 1152
#define NBE ((EDC * HIDDEN + 255) / 256)       // 900
#define NB_PREP (NBA + NBW + NBE)

__global__ __launch_bounds__(256) void prep_kernel(
    const float* __restrict__ M, const float* __restrict__ W1,
    const float* __restrict__ ed_table, const float* __restrict__ b1)
{
    __shared__ float t[32][33];
    const int bid = blockIdx.x;
    const int tid = threadIdx.x;

    if (bid < NBA) {
        int idx = bid * 256 + tid;
        int row = idx / HIDDEN;
        float v = (row < MROWS) ? M[idx] : 0.f;
        g_Ah[idx] = __float2half(v);
    } else if (bid < NBA + NBW) {
        const int bw = bid - NBA;
        const int kt = (bw % (HIDDEN / 32)) * 32;
        const int nt = (bw / (HIDDEN / 32)) * 32;
        const int x = tid & 31;
        const int y = tid >> 5;            // 0..7
        const int srcRowBase = (nt < HIDDEN) ? 0 : HIDDEN;
        const int srcCol     = ((nt < HIDDEN) ? nt : nt - HIDDEN) + x;
        #pragma unroll
        for (int r = y; r < 32; r += 8)
            t[r][x] = W1[(size_t)(srcRowBase + kt + r) * HIDDEN + srcCol];
        __syncthreads();
        #pragma unroll
        for (int r = y; r < 32; r += 8)
            g_Wt[(size_t)(nt + r) * HIDDEN + kt + x] = __float2half(t[x][r]);
    } else {
        int idx = (bid - NBA - NBW) * 256 + tid;
        if (idx < EDC * HIDDEN) {
            int e = idx / HIDDEN;
            int j = idx % HIDDEN;
            float s = b1[j];
            #pragma unroll
            for (int tt = 0; tt < META; tt++)
                s += ed_table[e * META + tt] * W1[(size_t)(2 * HIDDEN + tt) * HIDDEN + j];
            g_Eh[idx] = __float2half(s);
        }
    }
}

// ---------------------------------------------------------------------------
// fp16 mma.sync GEMM: P = A @ Wt^T, fp32 accum, fp16 store.
// 128x128 CTA tile, BK=32, 4-stage cp.async, 80B-padded smem rows.
// Whole-k-block fragment hoist (12 LDSM burst, then 32 HMMA).
// ---------------------------------------------------------------------------
#define BK 32
#define NBLK (HIDDEN / BK)          // 24
#define ROWB 80
#define TILEB (128 * ROWB)          // 10240
#define STAGEB (2 * TILEB)          // 20480 (A, B)
#define STAGES 4
#define GEMM_SMEM (STAGES * STAGEB) // 81920

static __device__ __forceinline__ uint32_t smem_u32(const void* p) {
    uint32_t a;
    asm("{ .reg .u64 t; cvta.to.shared.u64 t, %1; cvt.u32.u64 %0, t; }" : "=r"(a) : "l"(p));
    return a;
}
static __device__ __forceinline__ void cp16(uint32_t dst, const void* src) {
    asm volatile("cp.async.cg.shared.global [%0], [%1], 16;" :: "r"(dst), "l"(src));
}
static __device__ __forceinline__ void ldmx4(uint32_t& r0, uint32_t& r1,
                                             uint32_t& r2, uint32_t& r3, uint32_t a) {
    asm volatile("ldmatrix.sync.aligned.m8n8.x4.shared.b16 {%0,%1,%2,%3}, [%4];"
                 : "=r"(r0), "=r"(r1), "=r"(r2), "=r"(r3) : "r"(a));
}
static __device__ __forceinline__ void mma16816(float* c, const uint32_t* a, const uint32_t* b) {
    asm volatile(
        "mma.sync.aligned.m16n8k16.row.col.f32.f16.f16.f32 "
        "{%0,%1,%2,%3}, {%4,%5,%6,%7}, {%8,%9}, {%0,%1,%2,%3};"
        : "+f"(c[0]), "+f"(c[1]), "+f"(c[2]), "+f"(c[3])
        : "r"(a[0]), "r"(a[1]), "r"(a[2]), "r"(a[3]), "r"(b[0]), "r"(b[1]));
}

__global__ __launch_bounds__(256, 2) void mma_gemm_kernel() {
    extern __shared__ char smem[];
    const uint32_t sb = smem_u32(smem);
    const int tid = threadIdx.x;
    const int lane = tid & 31;
    const int wid = tid >> 5;
    const int m0 = blockIdx.y * 128;
    const int n0 = blockIdx.x * 128;
    const int warpM = wid & 1;       // 2 warps in M
    const int warpN = wid >> 1;      // 4 warps in N

    const int ldRow = tid >> 1;      // 0..127
    const int ldSeg = (tid & 1) * 2; // 0 or 2 (16B segs)

    float acc[4][4][4];
    #pragma unroll
    for (int i = 0; i < 4; i++)
        #pragma unroll
        for (int j = 0; j < 4; j++)
            #pragma unroll
            for (int q = 0; q < 4; q++) acc[i][j][q] = 0.f;

    auto issue_load = [&](int blk) {
        const int stage = blk % STAGES;
        const __half* ga = g_Ah + (size_t)(m0 + ldRow) * HIDDEN + blk * BK + ldSeg * 8;
        const __half* gb = g_Wt + (size_t)(n0 + ldRow) * HIDDEN + blk * BK + ldSeg * 8;
        uint32_t d = sb + stage * STAGEB + ldRow * ROWB + ldSeg * 16;
        cp16(d,         ga);  cp16(d + 16,         ga + 8);
        cp16(d + TILEB, gb);  cp16(d + TILEB + 16, gb + 8);
        asm volatile("cp.async.commit_group;" ::: "memory");
    };

    issue_load(0);
    issue_load(1);
    issue_load(2);

    // precomputed intra-tile ldmatrix offsets
    const uint32_t aoff = (warpM * 64 + (lane & 15)) * ROWB + (lane >> 4) * 16;
    const int gg = lane >> 3;
    const int rr = lane & 7;
    const uint32_t boff = (warpN * 32 + ((gg >> 1) * 8 + rr)) * ROWB + (gg & 1) * 16;

    for (int blk = 0; blk < NBLK; blk++) {
        const int stage = blk % STAGES;
        asm volatile("cp.async.wait_group 2;" ::: "memory");
        __syncthreads();
        if (blk + 3 < NBLK) issue_load(blk + 3);

        const uint32_t Ab = sb + stage * STAGEB;
        const uint32_t Bb = Ab + TILEB;

        // hoist ALL fragments for this k-block (2 x k16)
        uint32_t a[2][4][4], b[2][4][2];
        #pragma unroll
        for (int ks = 0; ks < 2; ks++) {
            const int kb = ks * 32;
            #pragma unroll
            for (int nf2 = 0; nf2 < 2; nf2++)
                ldmx4(b[ks][nf2 * 2][0], b[ks][nf2 * 2][1],
                      b[ks][nf2 * 2 + 1][0], b[ks][nf2 * 2 + 1][1],
                      Bb + boff + nf2 * 16 * ROWB + kb);
            #pragma unroll
            for (int mf = 0; mf < 4; mf++)
                ldmx4(a[ks][mf][0], a[ks][mf][1], a[ks][mf][2], a[ks][mf][3],
                      Ab + aoff + mf * 16 * ROWB + kb);
        }
        #pragma unroll
        for (int ks = 0; ks < 2; ks++)
            #pragma unroll
            for (int mf = 0; mf < 4; mf++)
                #pragma unroll
                for (int nf = 0; nf < 4; nf++)
                    mma16816(acc[mf][nf], a[ks][mf], b[ks][nf]);
    }

    // store P as fp16
    #pragma unroll
    for (int mf = 0; mf < 4; mf++) {
        const int r0 = m0 + warpM * 64 + mf * 16 + (lane >> 2);
        #pragma unroll
        for (int nf = 0; nf < 4; nf++) {
            const int c = n0 + warpN * 32 + nf * 8 + (lane & 3) * 2;
            if (r0 < MROWS)
                *(__half2*)(g_Ph + (size_t)r0 * NCOLS + c) =
                    __floats2half2_rn(acc[mf][nf][0], acc[mf][nf][1]);
            if (r0 + 8 < MROWS)
                *(__half2*)(g_Ph + (size_t)(r0 + 8) * NCOLS + c) =
                    __floats2half2_rn(acc[mf][nf][2], acc[mf][nf][3]);
        }
    }
}

// ---------------------------------------------------------------------------
// Epilogue: one warp per pair; P and E rows in fp16.
// ---------------------------------------------------------------------------
__global__ __launch_bounds__(256) void epilogue_kernel(
    const int* __restrict__ pairs, const int* __restrict__ eds,
    const float* __restrict__ W2, const float* __restrict__ b2,
    float* __restrict__ out)
{
    __shared__ float w2s[HIDDEN];
    const int tid = threadIdx.x;
    for (int i = tid; i < HIDDEN; i += 256) w2s[i] = W2[i];
    __syncthreads();

    const int warp = tid / 32;
    const int lane = tid % 32;
    const int p = blockIdx.x * 8 + warp;
    if (p >= BATCH * NPAIRS) return;

    const int b  = p / NPAIRS;
    const int i0 = pairs[(size_t)p * 2 + 0];
    const int i1 = pairs[(size_t)p * 2 + 1];
    const int e  = eds[p];

    const __half* rowA = g_Ph + (size_t)(b * NMENT + i0) * NCOLS;
    const __half* rowB = g_Ph + (size_t)(b * NMENT + i1) * NCOLS + HIDDEN;
    const __half* rowE = g_Eh + (size_t)e * HIDDEN;

    float acc = 0.f;
    #pragma unroll
    for (int j0 = 0; j0 < 3; j0++) {
        const int h0 = j0 * 256 + lane * 8;   // half index, 16B aligned
        uint4 ua = *(const uint4*)(rowA + h0);
        uint4 ub = *(const uint4*)(rowB + h0);
        uint4 ue = *(const uint4*)(rowE + h0);
        const __half2* ha = (const __half2*)&ua;
        const __half2* hb = (const __half2*)&ub;
        const __half2* he = (const __half2*)&ue;
        #pragma unroll
        for (int q = 0; q < 4; q++) {
            float2 fa = __half22float2(ha[q]);
            float2 fb = __half22float2(hb[q]);
            float2 fe = __half22float2(he[q]);
            float2 fw = *(const float2*)(&w2s[h0 + q * 2]);
            float v;
            v = fa.x + fb.x + fe.x; acc += fmaxf(v, 0.f) * fw.x;
            v = fa.y + fb.y + fe.y; acc += fmaxf(v, 0.f) * fw.y;
        }
    }
    #pragma unroll
    for (int off = 16; off; off >>= 1)
        acc += __shfl_xor_sync(0xffffffff, acc, off);
    if (lane == 0) out[p] = acc + b2[0];
}

// ---------------------------------------------------------------------------
extern "C" void kernel_launch(void* const* d_in, const int* in_sizes, int n_in,
                              void* d_out, int out_size) {
    const float* mention_reprs = (const float*)d_in[0];
    const int*   pairs         = (const int*)d_in[1];
    const int*   eds           = (const int*)d_in[2];
    const float* ed_table      = (const float*)d_in[3];
    const float* W1            = (const float*)d_in[4];
    const float* b1            = (const float*)d_in[5];
    const float* W2            = (const float*)d_in[6];
    const float* b2            = (const float*)d_in[7];
    float* out = (float*)d_out;

    cudaFuncSetAttribute(mma_gemm_kernel,
                         cudaFuncAttributeMaxDynamicSharedMemorySize, GEMM_SMEM);

    prep_kernel<<<NB_PREP, 256>>>(mention_reprs, W1, ed_table, b1);
    { dim3 grid(NCOLS / 128, MPAD / 128);  // (12, 32)
      mma_gemm_kernel<<<grid, 256, GEMM_SMEM>>>(); }
    { int npairs = BATCH * NPAIRS;
      epilogue_kernel<<<(npairs + 7) / 8, 256>>>(pairs, eds, W2, b2, out); }
}